// round 1
// baseline (speedup 1.0000x reference)
#include <cuda_runtime.h>
#include <math.h>

#define EMBED 512
#define HH    8
#define HD    64
#define NQ    2048
#define LK    2048
#define BB    4
#define MROWS (NQ * BB)   // 8192

// Scratch (allocation-free rule: __device__ globals)
__device__ float g_Qp[(size_t)MROWS * EMBED];
__device__ float g_Kp[(size_t)MROWS * EMBED];
__device__ float g_Vp[(size_t)MROWS * EMBED];
__device__ float g_At[(size_t)MROWS * EMBED];

// ---------------------------------------------------------------------------
// GEMM: C[r][e] = sum_c X[r][c] * W[e][c] + bias[e]
// X: (M,512) row-major, W: (512,512) row-major (nn.Linear weight), K=N=512.
// Tile: BM=BN=128, BK=8, 256 threads, 8x8 microtile (two 4-col groups).
// ---------------------------------------------------------------------------
#define GLDT 132   // padded smem row stride (conflict-free transpose stores)

__global__ __launch_bounds__(256, 2)
void gemm_xwT(const float* __restrict__ X, const float* __restrict__ W,
              const float* __restrict__ bias, float* __restrict__ C)
{
    __shared__ float As[8 * GLDT];
    __shared__ float Bs[8 * GLDT];

    const int tid = threadIdx.x;
    const int tx  = tid & 15;
    const int ty  = tid >> 4;
    const int r0  = blockIdx.y * 128;
    const int e0  = blockIdx.x * 128;
    const int lr  = tid >> 1;          // 0..127
    const int lk  = (tid & 1) * 4;     // 0 or 4

    const float* Xp = X + (size_t)(r0 + lr) * 512 + lk;
    const float* Wp = W + (size_t)(e0 + lr) * 512 + lk;

    float acc[8][8];
#pragma unroll
    for (int i = 0; i < 8; i++)
#pragma unroll
        for (int j = 0; j < 8; j++) acc[i][j] = 0.f;

    for (int kk = 0; kk < 512; kk += 8) {
        float4 xa = *(const float4*)(Xp + kk);
        float4 wa = *(const float4*)(Wp + kk);
        __syncthreads();
        As[(lk + 0) * GLDT + lr] = xa.x;
        As[(lk + 1) * GLDT + lr] = xa.y;
        As[(lk + 2) * GLDT + lr] = xa.z;
        As[(lk + 3) * GLDT + lr] = xa.w;
        Bs[(lk + 0) * GLDT + lr] = wa.x;
        Bs[(lk + 1) * GLDT + lr] = wa.y;
        Bs[(lk + 2) * GLDT + lr] = wa.z;
        Bs[(lk + 3) * GLDT + lr] = wa.w;
        __syncthreads();
#pragma unroll
        for (int k = 0; k < 8; k++) {
            float a[8], b[8];
            *(float4*)(a)     = *(const float4*)(&As[k * GLDT + ty * 4]);
            *(float4*)(a + 4) = *(const float4*)(&As[k * GLDT + 64 + ty * 4]);
            *(float4*)(b)     = *(const float4*)(&Bs[k * GLDT + tx * 4]);
            *(float4*)(b + 4) = *(const float4*)(&Bs[k * GLDT + 64 + tx * 4]);
#pragma unroll
            for (int i = 0; i < 8; i++)
#pragma unroll
                for (int j = 0; j < 8; j++)
                    acc[i][j] = fmaf(a[i], b[j], acc[i][j]);
        }
    }

    const float4 bv0 = *(const float4*)(&bias[e0 + tx * 4]);
    const float4 bv1 = *(const float4*)(&bias[e0 + 64 + tx * 4]);
#pragma unroll
    for (int i = 0; i < 8; i++) {
        const int r = r0 + ((i < 4) ? (ty * 4 + i) : (64 + ty * 4 + i - 4));
        float4 o0, o1;
        o0.x = acc[i][0] + bv0.x; o0.y = acc[i][1] + bv0.y;
        o0.z = acc[i][2] + bv0.z; o0.w = acc[i][3] + bv0.w;
        o1.x = acc[i][4] + bv1.x; o1.y = acc[i][5] + bv1.y;
        o1.z = acc[i][6] + bv1.z; o1.w = acc[i][7] + bv1.w;
        *(float4*)(&C[(size_t)r * 512 + e0 + tx * 4])      = o0;
        *(float4*)(&C[(size_t)r * 512 + e0 + 64 + tx * 4]) = o1;
    }
}

// ---------------------------------------------------------------------------
// Flash attention, fp32. One block handles 64 q-rows of one (b,h) pair.
// Q scaled by 1/8 at load; bias = (pe1/8)·pe2 computed in-register.
// Smem: Qt (d-major Q), KP (d-major K, later reused for P), Vs (natural V).
// 3 × 16 KB = 48 KB static smem exactly.
// ---------------------------------------------------------------------------
__global__ __launch_bounds__(256)
void attn_kernel(const float* __restrict__ pe1, const float* __restrict__ pe2)
{
    __shared__ float Qt[64 * 64];
    __shared__ float KP[64 * 64];
    __shared__ float Vs[64 * 64];

    const int tid = threadIdx.x;
    const int tx  = tid & 15;   // j / d column group (4 each)
    const int ty  = tid >> 4;   // i row group (4 each)
    const int bh  = blockIdx.y;
    const int b   = bh >> 3;    // H = 8
    const int h   = bh & 7;
    const int n0  = blockIdx.x * 64;

    const int li = tid & 63;          // row index for Q/K transpose loads
    const int ld = (tid >> 6) * 16;   // d base (0,16,32,48)

    // Load Q tile transposed (Qt[d][i]) with 1/sqrt(HD)=0.125 folded in.
    {
        const float* qb = g_Qp + ((size_t)(n0 + li) * BB + b) * 512 + h * HD + ld;
#pragma unroll
        for (int u = 0; u < 4; u++) {
            float4 t = *(const float4*)(qb + u * 4);
            Qt[(ld + u * 4 + 0) * 64 + li] = t.x * 0.125f;
            Qt[(ld + u * 4 + 1) * 64 + li] = t.y * 0.125f;
            Qt[(ld + u * 4 + 2) * 64 + li] = t.z * 0.125f;
            Qt[(ld + u * 4 + 3) * 64 + li] = t.w * 0.125f;
        }
    }

    // Per-thread pe1 rows (pre-scaled by 1/8)
    float pe1r[4][3];
#pragma unroll
    for (int ii = 0; ii < 4; ii++)
#pragma unroll
        for (int c = 0; c < 3; c++)
            pe1r[ii][c] = pe1[((size_t)b * NQ + n0 + ty * 4 + ii) * 3 + c] * 0.125f;

    float m[4], lsum[4], o[4][4];
#pragma unroll
    for (int ii = 0; ii < 4; ii++) {
        m[ii] = -INFINITY;
        lsum[ii] = 0.f;
#pragma unroll
        for (int dd = 0; dd < 4; dd++) o[ii][dd] = 0.f;
    }

    const int vj = tid >> 2;          // V row
    const int vd = (tid & 3) * 16;    // V d base

    for (int lt = 0; lt < LK / 64; lt++) {
        const int l0 = lt * 64;
        __syncthreads();  // prior-tile KP/Vs readers done before overwrite

        // K tile transposed (KP[d][j])
        {
            const float* kb = g_Kp + ((size_t)(l0 + li) * BB + b) * 512 + h * HD + ld;
#pragma unroll
            for (int u = 0; u < 4; u++) {
                float4 t = *(const float4*)(kb + u * 4);
                KP[(ld + u * 4 + 0) * 64 + li] = t.x;
                KP[(ld + u * 4 + 1) * 64 + li] = t.y;
                KP[(ld + u * 4 + 2) * 64 + li] = t.z;
                KP[(ld + u * 4 + 3) * 64 + li] = t.w;
            }
        }
        // V tile natural (Vs[j][d])
        {
            const float* vb = g_Vp + ((size_t)(l0 + vj) * BB + b) * 512 + h * HD + vd;
#pragma unroll
            for (int u = 0; u < 4; u++)
                *(float4*)(&Vs[vj * 64 + vd + u * 4]) = *(const float4*)(vb + u * 4);
        }
        // pe2 columns for this tile
        float pe2r[4][3];
#pragma unroll
        for (int jj = 0; jj < 4; jj++)
#pragma unroll
            for (int c = 0; c < 3; c++)
                pe2r[jj][c] = pe2[(size_t)(l0 + tx * 4 + jj) * 3 + c];
        __syncthreads();

        // S = (Q/8)·Kᵀ + (pe1/8)·pe2
        float s[4][4];
#pragma unroll
        for (int ii = 0; ii < 4; ii++)
#pragma unroll
            for (int jj = 0; jj < 4; jj++)
                s[ii][jj] = pe1r[ii][0] * pe2r[jj][0]
                          + pe1r[ii][1] * pe2r[jj][1]
                          + pe1r[ii][2] * pe2r[jj][2];

#pragma unroll 4
        for (int d = 0; d < 64; d++) {
            float4 qa = *(const float4*)(&Qt[d * 64 + ty * 4]);
            float4 ka = *(const float4*)(&KP[d * 64 + tx * 4]);
            s[0][0] = fmaf(qa.x, ka.x, s[0][0]); s[0][1] = fmaf(qa.x, ka.y, s[0][1]);
            s[0][2] = fmaf(qa.x, ka.z, s[0][2]); s[0][3] = fmaf(qa.x, ka.w, s[0][3]);
            s[1][0] = fmaf(qa.y, ka.x, s[1][0]); s[1][1] = fmaf(qa.y, ka.y, s[1][1]);
            s[1][2] = fmaf(qa.y, ka.z, s[1][2]); s[1][3] = fmaf(qa.y, ka.w, s[1][3]);
            s[2][0] = fmaf(qa.z, ka.x, s[2][0]); s[2][1] = fmaf(qa.z, ka.y, s[2][1]);
            s[2][2] = fmaf(qa.z, ka.z, s[2][2]); s[2][3] = fmaf(qa.z, ka.w, s[2][3]);
            s[3][0] = fmaf(qa.w, ka.x, s[3][0]); s[3][1] = fmaf(qa.w, ka.y, s[3][1]);
            s[3][2] = fmaf(qa.w, ka.z, s[3][2]); s[3][3] = fmaf(qa.w, ka.w, s[3][3]);
        }

        // Online softmax (row stats across the 16 tx lanes, shfl width 16)
        float mn[4], sc[4];
#pragma unroll
        for (int ii = 0; ii < 4; ii++) {
            float mt = fmaxf(fmaxf(s[ii][0], s[ii][1]), fmaxf(s[ii][2], s[ii][3]));
            mt = fmaxf(mt, __shfl_xor_sync(0xffffffffu, mt, 1, 16));
            mt = fmaxf(mt, __shfl_xor_sync(0xffffffffu, mt, 2, 16));
            mt = fmaxf(mt, __shfl_xor_sync(0xffffffffu, mt, 4, 16));
            mt = fmaxf(mt, __shfl_xor_sync(0xffffffffu, mt, 8, 16));
            mn[ii] = fmaxf(m[ii], mt);
            sc[ii] = __expf(m[ii] - mn[ii]);
            m[ii]  = mn[ii];
        }
#pragma unroll
        for (int ii = 0; ii < 4; ii++) {
            float rs = 0.f;
#pragma unroll
            for (int jj = 0; jj < 4; jj++) {
                s[ii][jj] = __expf(s[ii][jj] - mn[ii]);
                rs += s[ii][jj];
            }
            rs += __shfl_xor_sync(0xffffffffu, rs, 1, 16);
            rs += __shfl_xor_sync(0xffffffffu, rs, 2, 16);
            rs += __shfl_xor_sync(0xffffffffu, rs, 4, 16);
            rs += __shfl_xor_sync(0xffffffffu, rs, 8, 16);
            lsum[ii] = lsum[ii] * sc[ii] + rs;
#pragma unroll
            for (int dd = 0; dd < 4; dd++) o[ii][dd] *= sc[ii];
        }

        __syncthreads();  // all KP (K) readers done before P overwrite
#pragma unroll
        for (int ii = 0; ii < 4; ii++)
#pragma unroll
            for (int jj = 0; jj < 4; jj++)
                KP[(ty * 4 + ii) * 64 + tx * 4 + jj] = s[ii][jj];
        __syncthreads();

        // O += P·V
#pragma unroll 4
        for (int j = 0; j < 64; j++) {
            float4 vv = *(const float4*)(&Vs[j * 64 + tx * 4]);
#pragma unroll
            for (int ii = 0; ii < 4; ii++) {
                float p = KP[(ty * 4 + ii) * 64 + j];
                o[ii][0] = fmaf(p, vv.x, o[ii][0]);
                o[ii][1] = fmaf(p, vv.y, o[ii][1]);
                o[ii][2] = fmaf(p, vv.z, o[ii][2]);
                o[ii][3] = fmaf(p, vv.w, o[ii][3]);
            }
        }
    }

    // Normalize and write attention output into g_At (n,b,E layout)
#pragma unroll
    for (int ii = 0; ii < 4; ii++) {
        float inv = 1.0f / lsum[ii];
        float4 ov;
        ov.x = o[ii][0] * inv; ov.y = o[ii][1] * inv;
        ov.z = o[ii][2] * inv; ov.w = o[ii][3] * inv;
        *(float4*)(&g_At[((size_t)(n0 + ty * 4 + ii) * BB + b) * 512 + h * HD + tx * 4]) = ov;
    }
}

// ---------------------------------------------------------------------------
extern "C" void kernel_launch(void* const* d_in, const int* in_sizes, int n_in,
                              void* d_out, int out_size)
{
    const float* q   = (const float*)d_in[0];
    const float* k   = (const float*)d_in[1];
    const float* v   = (const float*)d_in[2];
    const float* pe1 = (const float*)d_in[3];
    const float* pe2 = (const float*)d_in[4];
    const float* Wq  = (const float*)d_in[5];
    const float* bq  = (const float*)d_in[6];
    const float* Wk  = (const float*)d_in[7];
    const float* bk  = (const float*)d_in[8];
    const float* Wv  = (const float*)d_in[9];
    const float* bv  = (const float*)d_in[10];
    const float* Wo  = (const float*)d_in[11];
    const float* bo  = (const float*)d_in[12];
    float* out = (float*)d_out;

    float *Qp, *Kp, *Vp, *At;
    cudaGetSymbolAddress((void**)&Qp, g_Qp);
    cudaGetSymbolAddress((void**)&Kp, g_Kp);
    cudaGetSymbolAddress((void**)&Vp, g_Vp);
    cudaGetSymbolAddress((void**)&At, g_At);

    dim3 gg(512 / 128, MROWS / 128);   // (4, 64)
    gemm_xwT<<<gg, 256>>>(q, Wq, bq, Qp);
    gemm_xwT<<<gg, 256>>>(k, Wk, bk, Kp);
    gemm_xwT<<<gg, 256>>>(v, Wv, bv, Vp);

    dim3 ga(NQ / 64, BB * HH);         // (32, 32)
    attn_kernel<<<ga, 256>>>(pe1, pe2);

    gemm_xwT<<<gg, 256>>>(At, Wo, bo, out);
}

// round 2
// speedup vs baseline: 1.0001x; 1.0001x over previous
#include <cuda_runtime.h>
#include <math.h>

#define EMBED 512
#define HH    8
#define HD    64
#define NQ    2048
#define LK    2048
#define BB    4
#define MROWS (NQ * BB)   // 8192

// Scratch (allocation-free rule: __device__ globals)
__device__ float g_Qp[(size_t)MROWS * EMBED];
__device__ float g_Kp[(size_t)MROWS * EMBED];
__device__ float g_Vp[(size_t)MROWS * EMBED];
__device__ float g_At[(size_t)MROWS * EMBED];

// ---------------------------------------------------------------------------
// GEMM: C[r][e] = sum_c X[r][c] * W[e][c] + bias[e]
// X: (M,512) row-major, W: (512,512) row-major (nn.Linear weight), K=N=512.
// Tile: BM=BN=128, BK=8, 256 threads, 8x8 microtile (two 4-col groups).
// ---------------------------------------------------------------------------
#define GLDT 132   // padded smem row stride (conflict-free transpose stores)

__global__ __launch_bounds__(256, 2)
void gemm_xwT(const float* __restrict__ X, const float* __restrict__ W,
              const float* __restrict__ bias, float* __restrict__ C)
{
    __shared__ float As[8 * GLDT];
    __shared__ float Bs[8 * GLDT];

    const int tid = threadIdx.x;
    const int tx  = tid & 15;
    const int ty  = tid >> 4;
    const int r0  = blockIdx.y * 128;
    const int e0  = blockIdx.x * 128;
    const int lr  = tid >> 1;          // 0..127
    const int lk  = (tid & 1) * 4;     // 0 or 4

    const float* Xp = X + (size_t)(r0 + lr) * 512 + lk;
    const float* Wp = W + (size_t)(e0 + lr) * 512 + lk;

    float acc[8][8];
#pragma unroll
    for (int i = 0; i < 8; i++)
#pragma unroll
        for (int j = 0; j < 8; j++) acc[i][j] = 0.f;

    for (int kk = 0; kk < 512; kk += 8) {
        float4 xa = *(const float4*)(Xp + kk);
        float4 wa = *(const float4*)(Wp + kk);
        __syncthreads();
        As[(lk + 0) * GLDT + lr] = xa.x;
        As[(lk + 1) * GLDT + lr] = xa.y;
        As[(lk + 2) * GLDT + lr] = xa.z;
        As[(lk + 3) * GLDT + lr] = xa.w;
        Bs[(lk + 0) * GLDT + lr] = wa.x;
        Bs[(lk + 1) * GLDT + lr] = wa.y;
        Bs[(lk + 2) * GLDT + lr] = wa.z;
        Bs[(lk + 3) * GLDT + lr] = wa.w;
        __syncthreads();
#pragma unroll
        for (int k = 0; k < 8; k++) {
            float a[8], b[8];
            *(float4*)(a)     = *(const float4*)(&As[k * GLDT + ty * 4]);
            *(float4*)(a + 4) = *(const float4*)(&As[k * GLDT + 64 + ty * 4]);
            *(float4*)(b)     = *(const float4*)(&Bs[k * GLDT + tx * 4]);
            *(float4*)(b + 4) = *(const float4*)(&Bs[k * GLDT + 64 + tx * 4]);
#pragma unroll
            for (int i = 0; i < 8; i++)
#pragma unroll
                for (int j = 0; j < 8; j++)
                    acc[i][j] = fmaf(a[i], b[j], acc[i][j]);
        }
    }

    const float4 bv0 = *(const float4*)(&bias[e0 + tx * 4]);
    const float4 bv1 = *(const float4*)(&bias[e0 + 64 + tx * 4]);
#pragma unroll
    for (int i = 0; i < 8; i++) {
        const int r = r0 + ((i < 4) ? (ty * 4 + i) : (64 + ty * 4 + i - 4));
        float4 o0, o1;
        o0.x = acc[i][0] + bv0.x; o0.y = acc[i][1] + bv0.y;
        o0.z = acc[i][2] + bv0.z; o0.w = acc[i][3] + bv0.w;
        o1.x = acc[i][4] + bv1.x; o1.y = acc[i][5] + bv1.y;
        o1.z = acc[i][6] + bv1.z; o1.w = acc[i][7] + bv1.w;
        *(float4*)(&C[(size_t)r * 512 + e0 + tx * 4])      = o0;
        *(float4*)(&C[(size_t)r * 512 + e0 + 64 + tx * 4]) = o1;
    }
}

// ---------------------------------------------------------------------------
// Flash attention, fp32. One block handles 64 q-rows of one (b,h) pair.
// Q scaled by 1/8 at load; bias = (pe1/8)·pe2 computed in-register.
// Smem: Qt (d-major Q), KP (d-major K, later reused for P), Vs (natural V).
// 3 × 16 KB = 48 KB static smem exactly.
// ---------------------------------------------------------------------------
__global__ __launch_bounds__(256)
void attn_kernel(const float* __restrict__ pe1, const float* __restrict__ pe2)
{
    __shared__ float Qt[64 * 64];
    __shared__ float KP[64 * 64];
    __shared__ float Vs[64 * 64];

    const int tid = threadIdx.x;
    const int tx  = tid & 15;   // j / d column group (4 each)
    const int ty  = tid >> 4;   // i row group (4 each)
    const int bh  = blockIdx.y;
    const int b   = bh >> 3;    // H = 8
    const int h   = bh & 7;
    const int n0  = blockIdx.x * 64;

    const int li = tid & 63;          // row index for Q/K transpose loads
    const int ld = (tid >> 6) * 16;   // d base (0,16,32,48)

    // Load Q tile transposed (Qt[d][i]) with 1/sqrt(HD)=0.125 folded in.
    {
        const float* qb = g_Qp + ((size_t)(n0 + li) * BB + b) * 512 + h * HD + ld;
#pragma unroll
        for (int u = 0; u < 4; u++) {
            float4 t = *(const float4*)(qb + u * 4);
            Qt[(ld + u * 4 + 0) * 64 + li] = t.x * 0.125f;
            Qt[(ld + u * 4 + 1) * 64 + li] = t.y * 0.125f;
            Qt[(ld + u * 4 + 2) * 64 + li] = t.z * 0.125f;
            Qt[(ld + u * 4 + 3) * 64 + li] = t.w * 0.125f;
        }
    }

    // Per-thread pe1 rows (pre-scaled by 1/8)
    float pe1r[4][3];
#pragma unroll
    for (int ii = 0; ii < 4; ii++)
#pragma unroll
        for (int c = 0; c < 3; c++)
            pe1r[ii][c] = pe1[((size_t)b * NQ + n0 + ty * 4 + ii) * 3 + c] * 0.125f;

    float m[4], lsum[4], o[4][4];
#pragma unroll
    for (int ii = 0; ii < 4; ii++) {
        m[ii] = -INFINITY;
        lsum[ii] = 0.f;
#pragma unroll
        for (int dd = 0; dd < 4; dd++) o[ii][dd] = 0.f;
    }

    const int vj = tid >> 2;          // V row
    const int vd = (tid & 3) * 16;    // V d base

    for (int lt = 0; lt < LK / 64; lt++) {
        const int l0 = lt * 64;
        __syncthreads();  // prior-tile KP/Vs readers done before overwrite

        // K tile transposed (KP[d][j])
        {
            const float* kb = g_Kp + ((size_t)(l0 + li) * BB + b) * 512 + h * HD + ld;
#pragma unroll
            for (int u = 0; u < 4; u++) {
                float4 t = *(const float4*)(kb + u * 4);
                KP[(ld + u * 4 + 0) * 64 + li] = t.x;
                KP[(ld + u * 4 + 1) * 64 + li] = t.y;
                KP[(ld + u * 4 + 2) * 64 + li] = t.z;
                KP[(ld + u * 4 + 3) * 64 + li] = t.w;
            }
        }
        // V tile natural (Vs[j][d])
        {
            const float* vb = g_Vp + ((size_t)(l0 + vj) * BB + b) * 512 + h * HD + vd;
#pragma unroll
            for (int u = 0; u < 4; u++)
                *(float4*)(&Vs[vj * 64 + vd + u * 4]) = *(const float4*)(vb + u * 4);
        }
        // pe2 columns for this tile
        float pe2r[4][3];
#pragma unroll
        for (int jj = 0; jj < 4; jj++)
#pragma unroll
            for (int c = 0; c < 3; c++)
                pe2r[jj][c] = pe2[(size_t)(l0 + tx * 4 + jj) * 3 + c];
        __syncthreads();

        // S = (Q/8)·Kᵀ + (pe1/8)·pe2
        float s[4][4];
#pragma unroll
        for (int ii = 0; ii < 4; ii++)
#pragma unroll
            for (int jj = 0; jj < 4; jj++)
                s[ii][jj] = pe1r[ii][0] * pe2r[jj][0]
                          + pe1r[ii][1] * pe2r[jj][1]
                          + pe1r[ii][2] * pe2r[jj][2];

#pragma unroll 4
        for (int d = 0; d < 64; d++) {
            float4 qa = *(const float4*)(&Qt[d * 64 + ty * 4]);
            float4 ka = *(const float4*)(&KP[d * 64 + tx * 4]);
            s[0][0] = fmaf(qa.x, ka.x, s[0][0]); s[0][1] = fmaf(qa.x, ka.y, s[0][1]);
            s[0][2] = fmaf(qa.x, ka.z, s[0][2]); s[0][3] = fmaf(qa.x, ka.w, s[0][3]);
            s[1][0] = fmaf(qa.y, ka.x, s[1][0]); s[1][1] = fmaf(qa.y, ka.y, s[1][1]);
            s[1][2] = fmaf(qa.y, ka.z, s[1][2]); s[1][3] = fmaf(qa.y, ka.w, s[1][3]);
            s[2][0] = fmaf(qa.z, ka.x, s[2][0]); s[2][1] = fmaf(qa.z, ka.y, s[2][1]);
            s[2][2] = fmaf(qa.z, ka.z, s[2][2]); s[2][3] = fmaf(qa.z, ka.w, s[2][3]);
            s[3][0] = fmaf(qa.w, ka.x, s[3][0]); s[3][1] = fmaf(qa.w, ka.y, s[3][1]);
            s[3][2] = fmaf(qa.w, ka.z, s[3][2]); s[3][3] = fmaf(qa.w, ka.w, s[3][3]);
        }

        // Online softmax (row stats across the 16 tx lanes, shfl width 16)
        float mn[4], sc[4];
#pragma unroll
        for (int ii = 0; ii < 4; ii++) {
            float mt = fmaxf(fmaxf(s[ii][0], s[ii][1]), fmaxf(s[ii][2], s[ii][3]));
            mt = fmaxf(mt, __shfl_xor_sync(0xffffffffu, mt, 1, 16));
            mt = fmaxf(mt, __shfl_xor_sync(0xffffffffu, mt, 2, 16));
            mt = fmaxf(mt, __shfl_xor_sync(0xffffffffu, mt, 4, 16));
            mt = fmaxf(mt, __shfl_xor_sync(0xffffffffu, mt, 8, 16));
            mn[ii] = fmaxf(m[ii], mt);
            sc[ii] = __expf(m[ii] - mn[ii]);
            m[ii]  = mn[ii];
        }
#pragma unroll
        for (int ii = 0; ii < 4; ii++) {
            float rs = 0.f;
#pragma unroll
            for (int jj = 0; jj < 4; jj++) {
                s[ii][jj] = __expf(s[ii][jj] - mn[ii]);
                rs += s[ii][jj];
            }
            rs += __shfl_xor_sync(0xffffffffu, rs, 1, 16);
            rs += __shfl_xor_sync(0xffffffffu, rs, 2, 16);
            rs += __shfl_xor_sync(0xffffffffu, rs, 4, 16);
            rs += __shfl_xor_sync(0xffffffffu, rs, 8, 16);
            lsum[ii] = lsum[ii] * sc[ii] + rs;
#pragma unroll
            for (int dd = 0; dd < 4; dd++) o[ii][dd] *= sc[ii];
        }

        __syncthreads();  // all KP (K) readers done before P overwrite
#pragma unroll
        for (int ii = 0; ii < 4; ii++)
#pragma unroll
            for (int jj = 0; jj < 4; jj++)
                KP[(ty * 4 + ii) * 64 + tx * 4 + jj] = s[ii][jj];
        __syncthreads();

        // O += P·V
#pragma unroll 4
        for (int j = 0; j < 64; j++) {
            float4 vv = *(const float4*)(&Vs[j * 64 + tx * 4]);
#pragma unroll
            for (int ii = 0; ii < 4; ii++) {
                float p = KP[(ty * 4 + ii) * 64 + j];
                o[ii][0] = fmaf(p, vv.x, o[ii][0]);
                o[ii][1] = fmaf(p, vv.y, o[ii][1]);
                o[ii][2] = fmaf(p, vv.z, o[ii][2]);
                o[ii][3] = fmaf(p, vv.w, o[ii][3]);
            }
        }
    }

    // Normalize and write attention output into g_At (n,b,E layout)
#pragma unroll
    for (int ii = 0; ii < 4; ii++) {
        float inv = 1.0f / lsum[ii];
        float4 ov;
        ov.x = o[ii][0] * inv; ov.y = o[ii][1] * inv;
        ov.z = o[ii][2] * inv; ov.w = o[ii][3] * inv;
        *(float4*)(&g_At[((size_t)(n0 + ty * 4 + ii) * BB + b) * 512 + h * HD + tx * 4]) = ov;
    }
}

// ---------------------------------------------------------------------------
extern "C" void kernel_launch(void* const* d_in, const int* in_sizes, int n_in,
                              void* d_out, int out_size)
{
    const float* q   = (const float*)d_in[0];
    const float* k   = (const float*)d_in[1];
    const float* v   = (const float*)d_in[2];
    const float* pe1 = (const float*)d_in[3];
    const float* pe2 = (const float*)d_in[4];
    const float* Wq  = (const float*)d_in[5];
    const float* bq  = (const float*)d_in[6];
    const float* Wk  = (const float*)d_in[7];
    const float* bk  = (const float*)d_in[8];
    const float* Wv  = (const float*)d_in[9];
    const float* bv  = (const float*)d_in[10];
    const float* Wo  = (const float*)d_in[11];
    const float* bo  = (const float*)d_in[12];
    float* out = (float*)d_out;

    float *Qp, *Kp, *Vp, *At;
    cudaGetSymbolAddress((void**)&Qp, g_Qp);
    cudaGetSymbolAddress((void**)&Kp, g_Kp);
    cudaGetSymbolAddress((void**)&Vp, g_Vp);
    cudaGetSymbolAddress((void**)&At, g_At);

    dim3 gg(512 / 128, MROWS / 128);   // (4, 64)
    gemm_xwT<<<gg, 256>>>(q, Wq, bq, Qp);
    gemm_xwT<<<gg, 256>>>(k, Wk, bk, Kp);
    gemm_xwT<<<gg, 256>>>(v, Wv, bv, Vp);

    dim3 ga(NQ / 64, BB * HH);         // (32, 32)
    attn_kernel<<<ga, 256>>>(pe1, pe2);

    gemm_xwT<<<gg, 256>>>(At, Wo, bo, out);
}